// round 1
// baseline (speedup 1.0000x reference)
#include <cuda_runtime.h>
#include <math.h>

#define D 128
#define HID 64
#define MAX_NODES 50000

// Scratch: per-node projections. P[i][0:64] = embeds[i] @ W1[0:128,:]
//                                P[i][64:128] = embeds[i] @ W1[128:256,:]
__device__ float g_P[(size_t)MAX_NODES * 2 * HID];
// Constant part: embeds[n] @ W1[256:384,:] + b1
__device__ float g_cvec[HID];

// ---------------------------------------------------------------------------
// K0: cvec[j] = b1[j] + sum_k embeds[n][k] * W1[(256+k)*64 + j]
// ---------------------------------------------------------------------------
__global__ void cvec_kernel(const float* __restrict__ embeds,
                            const float* __restrict__ W1,
                            const float* __restrict__ b1,
                            const int* __restrict__ n_ptr) {
    int j = threadIdx.x;           // 0..63
    int n = n_ptr[0];
    const float* e = embeds + (size_t)n * D;
    float acc = b1[j];
#pragma unroll 8
    for (int k = 0; k < D; k++)
        acc = fmaf(e[k], W1[(2 * D + k) * HID + j], acc);
    g_cvec[j] = acc;
}

// ---------------------------------------------------------------------------
// K1: P = embeds @ [W1a | W1b]   (M=n_nodes, N=128, K=128)
// 256 threads, 128x128 tile, 8x8 register tile per thread, K-chunks of 16.
// ---------------------------------------------------------------------------
__global__ void proj_kernel(const float* __restrict__ embeds,
                            const float* __restrict__ W1,
                            int n_nodes) {
    __shared__ float As[16][128];   // As[k][m] (A transposed for broadcast reads)
    __shared__ float Bs[16][128];   // Bs[k][n]

    const int tid = threadIdx.x;
    const int tx = tid & 15;        // 0..15 -> output cols tx*8..tx*8+7
    const int ty = tid >> 4;        // 0..15 -> output rows ty*8..ty*8+7
    const int rowBase = blockIdx.x * 128;

    float acc[8][8];
#pragma unroll
    for (int i = 0; i < 8; i++)
#pragma unroll
        for (int j = 0; j < 8; j++) acc[i][j] = 0.f;

    for (int kc = 0; kc < D; kc += 16) {
        // --- load A tile: 128 rows x 16 k = 512 float4, 2 per thread ---
#pragma unroll
        for (int i = 0; i < 2; i++) {
            int f = tid + i * 256;          // 0..511
            int r = f >> 2;                 // row within tile
            int k4 = f & 3;                 // which float4 within the 16 k's
            float4 v = make_float4(0.f, 0.f, 0.f, 0.f);
            int gr = rowBase + r;
            if (gr < n_nodes)
                v = *(const float4*)&embeds[(size_t)gr * D + kc + k4 * 4];
            As[k4 * 4 + 0][r] = v.x;
            As[k4 * 4 + 1][r] = v.y;
            As[k4 * 4 + 2][r] = v.z;
            As[k4 * 4 + 3][r] = v.w;
        }
        // --- load B tile: 16 k x 128 cols, 8 scalars per thread ---
#pragma unroll
        for (int i = 0; i < 8; i++) {
            int f = tid + i * 256;          // 0..2047
            int kk = f >> 7;                // 0..15
            int j2 = f & 127;               // 0..127
            int kg = kc + kk;
            Bs[kk][j2] = (j2 < HID) ? W1[kg * HID + j2]
                                    : W1[(D + kg) * HID + (j2 - HID)];
        }
        __syncthreads();

#pragma unroll
        for (int kk = 0; kk < 16; kk++) {
            float a[8], b[8];
#pragma unroll
            for (int i = 0; i < 8; i++) a[i] = As[kk][ty * 8 + i];
#pragma unroll
            for (int j = 0; j < 8; j++) b[j] = Bs[kk][tx * 8 + j];
#pragma unroll
            for (int i = 0; i < 8; i++)
#pragma unroll
                for (int j = 0; j < 8; j++)
                    acc[i][j] = fmaf(a[i], b[j], acc[i][j]);
        }
        __syncthreads();
    }

    // --- store 8x8 per thread as float4 pairs ---
#pragma unroll
    for (int i = 0; i < 8; i++) {
        int r = rowBase + ty * 8 + i;
        if (r < n_nodes) {
            float* p = &g_P[(size_t)r * 128 + tx * 8];
            *(float4*)(p + 0) = make_float4(acc[i][0], acc[i][1], acc[i][2], acc[i][3]);
            *(float4*)(p + 4) = make_float4(acc[i][4], acc[i][5], acc[i][6], acc[i][7]);
        }
    }
}

// ---------------------------------------------------------------------------
// K2: one warp per edge.
//   h_j = relu(P[src][j] + P[dst][64+j] + cvec[j]),  j = lane, lane+32
//   sw  = sum_j h_j * W2[j] + b2
//   eps = -0.9998*u + 0.9999 ; gate = log(eps) - log1p(-eps)
//   out = sigmoid((gate + sw) / 5)
// ---------------------------------------------------------------------------
__global__ void edge_kernel(const float* __restrict__ W2,
                            const float* __restrict__ b2,
                            const float* __restrict__ u,
                            const int* __restrict__ src,
                            const int* __restrict__ dst,
                            float* __restrict__ out,
                            int E) {
    int warp = (int)((blockIdx.x * blockDim.x + threadIdx.x) >> 5);
    int lane = threadIdx.x & 31;
    if (warp >= E) return;

    int s = __ldg(&src[warp]);
    int d = __ldg(&dst[warp]);
    const float* Ps = g_P + (size_t)s * 128;        // row-part [0:64]
    const float* Pd = g_P + (size_t)d * 128 + 64;   // col-part [64:128]

    float h0 = Ps[lane]      + Pd[lane]      + g_cvec[lane];
    float h1 = Ps[lane + 32] + Pd[lane + 32] + g_cvec[lane + 32];
    h0 = fmaxf(h0, 0.f);
    h1 = fmaxf(h1, 0.f);
    float p = fmaf(h0, __ldg(&W2[lane]), h1 * __ldg(&W2[lane + 32]));

#pragma unroll
    for (int off = 16; off; off >>= 1)
        p += __shfl_xor_sync(0xffffffffu, p, off);

    if (lane == 0) {
        float sw = p + __ldg(&b2[0]);
        float eps = fmaf(-0.9998f, __ldg(&u[warp]), 0.9999f);
        float gate = logf(eps) - log1pf(-eps);
        float x = (gate + sw) * 0.2f;               // TEMP = 5
        out[warp] = 1.f / (1.f + expf(-x));
    }
}

// ---------------------------------------------------------------------------
// Inputs (metadata order): embeds, W1, b1, W2, b2, u, src, dst, n
// ---------------------------------------------------------------------------
extern "C" void kernel_launch(void* const* d_in, const int* in_sizes, int n_in,
                              void* d_out, int out_size) {
    const float* embeds = (const float*)d_in[0];
    const float* W1     = (const float*)d_in[1];
    const float* b1     = (const float*)d_in[2];
    const float* W2     = (const float*)d_in[3];
    const float* b2     = (const float*)d_in[4];
    const float* u      = (const float*)d_in[5];
    const int*   src    = (const int*)d_in[6];
    const int*   dst    = (const int*)d_in[7];
    const int*   n_ptr  = (const int*)d_in[8];

    int n_nodes = in_sizes[0] / D;
    int E       = in_sizes[6];

    cvec_kernel<<<1, HID>>>(embeds, W1, b1, n_ptr);
    proj_kernel<<<(n_nodes + 127) / 128, 256>>>(embeds, W1, n_nodes);
    edge_kernel<<<(E + 7) / 8, 256>>>(W2, b2, u, src, dst, (float*)d_out, E);
}

// round 2
// speedup vs baseline: 1.0273x; 1.0273x over previous
#include <cuda_runtime.h>
#include <cuda_bf16.h>
#include <math.h>

#define D 128
#define HID 64
#define MAX_NODES 50000

// Per-node projections stored in bf16: P[i][0:64] = embeds[i] @ W1[0:128,:]
//                                      P[i][64:128] = embeds[i] @ W1[128:256,:]
__device__ __nv_bfloat16 g_Pb[(size_t)MAX_NODES * 2 * HID];
// Constant part: embeds[n] @ W1[256:384,:] + b1  (fp32)
__device__ float g_cvec[HID];

// ---------------------------------------------------------------------------
// K0: cvec[j] = b1[j] + sum_k embeds[n][k] * W1[(256+k)*64 + j]
// 256 threads = 4 k-slices x 64 j. Coalesced W1 loads, smem reduce.
// ---------------------------------------------------------------------------
__global__ void cvec_kernel(const float* __restrict__ embeds,
                            const float* __restrict__ W1,
                            const float* __restrict__ b1,
                            const int* __restrict__ n_ptr) {
    __shared__ float red[4][HID];
    int tid = threadIdx.x;
    int t = tid >> 6;              // 0..3  (k slice)
    int j = tid & 63;              // 0..63 (output)
    int n = n_ptr[0];
    const float* e = embeds + (size_t)n * D;
    float acc = 0.f;
#pragma unroll 8
    for (int k = t * 32; k < t * 32 + 32; k++)
        acc = fmaf(e[k], W1[(2 * D + k) * HID + j], acc);
    red[t][j] = acc;
    __syncthreads();
    if (t == 0)
        g_cvec[j] = b1[j] + red[0][j] + red[1][j] + red[2][j] + red[3][j];
}

// ---------------------------------------------------------------------------
// K1: P = embeds @ [W1a | W1b]   (M=n_nodes, N=128, K=128), bf16 output.
// 256 threads, 128x128 tile, 8x8 register tile per thread, K-chunks of 16.
// ---------------------------------------------------------------------------
__global__ void proj_kernel(const float* __restrict__ embeds,
                            const float* __restrict__ W1,
                            int n_nodes) {
    __shared__ float As[16][128];   // As[k][m]
    __shared__ float Bs[16][128];   // Bs[k][n]

    const int tid = threadIdx.x;
    const int tx = tid & 15;
    const int ty = tid >> 4;
    const int rowBase = blockIdx.x * 128;

    float acc[8][8];
#pragma unroll
    for (int i = 0; i < 8; i++)
#pragma unroll
        for (int j = 0; j < 8; j++) acc[i][j] = 0.f;

    for (int kc = 0; kc < D; kc += 16) {
#pragma unroll
        for (int i = 0; i < 2; i++) {
            int f = tid + i * 256;
            int r = f >> 2;
            int k4 = f & 3;
            float4 v = make_float4(0.f, 0.f, 0.f, 0.f);
            int gr = rowBase + r;
            if (gr < n_nodes)
                v = *(const float4*)&embeds[(size_t)gr * D + kc + k4 * 4];
            As[k4 * 4 + 0][r] = v.x;
            As[k4 * 4 + 1][r] = v.y;
            As[k4 * 4 + 2][r] = v.z;
            As[k4 * 4 + 3][r] = v.w;
        }
#pragma unroll
        for (int i = 0; i < 8; i++) {
            int f = tid + i * 256;
            int kk = f >> 7;
            int j2 = f & 127;
            int kg = kc + kk;
            Bs[kk][j2] = (j2 < HID) ? W1[kg * HID + j2]
                                    : W1[(D + kg) * HID + (j2 - HID)];
        }
        __syncthreads();

#pragma unroll
        for (int kk = 0; kk < 16; kk++) {
            float a[8], b[8];
#pragma unroll
            for (int i = 0; i < 8; i++) a[i] = As[kk][ty * 8 + i];
#pragma unroll
            for (int j = 0; j < 8; j++) b[j] = Bs[kk][tx * 8 + j];
#pragma unroll
            for (int i = 0; i < 8; i++)
#pragma unroll
                for (int j = 0; j < 8; j++)
                    acc[i][j] = fmaf(a[i], b[j], acc[i][j]);
        }
        __syncthreads();
    }

    // --- store 8x8 per thread as bf16 (4x bfloat162 = 16B per row-chunk) ---
#pragma unroll
    for (int i = 0; i < 8; i++) {
        int r = rowBase + ty * 8 + i;
        if (r < n_nodes) {
            __nv_bfloat162* p = (__nv_bfloat162*)&g_Pb[(size_t)r * 128 + tx * 8];
            p[0] = __floats2bfloat162_rn(acc[i][0], acc[i][1]);
            p[1] = __floats2bfloat162_rn(acc[i][2], acc[i][3]);
            p[2] = __floats2bfloat162_rn(acc[i][4], acc[i][5]);
            p[3] = __floats2bfloat162_rn(acc[i][6], acc[i][7]);
        }
    }
}

// ---------------------------------------------------------------------------
// K2: one warp per edge, bf16 P gathers (128B per pointer, coalesced).
//   lane handles elements 2*lane, 2*lane+1 of the 64-wide hidden vector.
// ---------------------------------------------------------------------------
__global__ void edge_kernel(const float* __restrict__ W2,
                            const float* __restrict__ b2,
                            const float* __restrict__ u,
                            const int* __restrict__ src,
                            const int* __restrict__ dst,
                            float* __restrict__ out,
                            int E) {
    int warp = (int)((blockIdx.x * blockDim.x + threadIdx.x) >> 5);
    int lane = threadIdx.x & 31;
    if (warp >= E) return;

    int s = __ldg(&src[warp]);
    int d = __ldg(&dst[warp]);
    const __nv_bfloat162* Ps2 = (const __nv_bfloat162*)(g_Pb + (size_t)s * 128);
    const __nv_bfloat162* Pd2 = (const __nv_bfloat162*)(g_Pb + (size_t)d * 128 + 64);

    float2 ps = __bfloat1622float2(Ps2[lane]);
    float2 pd = __bfloat1622float2(Pd2[lane]);
    float2 c  = *(const float2*)&g_cvec[2 * lane];
    float2 w  = *(const float2*)&W2[2 * lane];

    float h0 = fmaxf(ps.x + pd.x + c.x, 0.f);
    float h1 = fmaxf(ps.y + pd.y + c.y, 0.f);
    float p = fmaf(h0, w.x, h1 * w.y);

#pragma unroll
    for (int off = 16; off; off >>= 1)
        p += __shfl_xor_sync(0xffffffffu, p, off);

    if (lane == 0) {
        float sw = p + __ldg(&b2[0]);
        float eps = fmaf(-0.9998f, __ldg(&u[warp]), 0.9999f);
        float gate = logf(eps) - log1pf(-eps);
        float x = (gate + sw) * 0.2f;               // TEMP = 5
        out[warp] = 1.f / (1.f + expf(-x));
    }
}

// ---------------------------------------------------------------------------
// Inputs (metadata order): embeds, W1, b1, W2, b2, u, src, dst, n
// ---------------------------------------------------------------------------
extern "C" void kernel_launch(void* const* d_in, const int* in_sizes, int n_in,
                              void* d_out, int out_size) {
    const float* embeds = (const float*)d_in[0];
    const float* W1     = (const float*)d_in[1];
    const float* b1     = (const float*)d_in[2];
    const float* W2     = (const float*)d_in[3];
    const float* b2     = (const float*)d_in[4];
    const float* u      = (const float*)d_in[5];
    const int*   src    = (const int*)d_in[6];
    const int*   dst    = (const int*)d_in[7];
    const int*   n_ptr  = (const int*)d_in[8];

    int n_nodes = in_sizes[0] / D;
    int E       = in_sizes[6];

    cvec_kernel<<<1, 256>>>(embeds, W1, b1, n_ptr);
    proj_kernel<<<(n_nodes + 127) / 128, 256>>>(embeds, W1, n_nodes);
    edge_kernel<<<(E + 7) / 8, 256>>>(W2, b2, u, src, dst, (float*)d_out, E);
}

// round 4
// speedup vs baseline: 1.4101x; 1.3726x over previous
#include <cuda_runtime.h>
#include <cuda_bf16.h>
#include <cstdint>
#include <math.h>

typedef unsigned int u32;

#define D 128
#define HID 64
#define MAX_NODES 50000

// Per-node projections in bf16: P[i][0:64] = embeds[i] @ W1[0:128,:]
//                               P[i][64:128] = embeds[i] @ W1[128:256,:]
__device__ __nv_bfloat16 g_Pb[(size_t)MAX_NODES * 2 * HID];
// Constant part: embeds[n] @ W1[256:384,:] + b1  (fp32)
__device__ float g_cvec[HID];

// ---------------------------------------------------------------------------
// K0: cvec[j] = b1[j] + sum_k embeds[n][k] * W1[(256+k)*64 + j]
// ---------------------------------------------------------------------------
__global__ void cvec_kernel(const float* __restrict__ embeds,
                            const float* __restrict__ W1,
                            const float* __restrict__ b1,
                            const int* __restrict__ n_ptr) {
    __shared__ float red[4][HID];
    int tid = threadIdx.x;
    int t = tid >> 6;
    int j = tid & 63;
    int n = n_ptr[0];
    const float* e = embeds + (size_t)n * D;
    float acc = 0.f;
#pragma unroll 8
    for (int k = t * 32; k < t * 32 + 32; k++)
        acc = fmaf(e[k], W1[(2 * D + k) * HID + j], acc);
    red[t][j] = acc;
    __syncthreads();
    if (t == 0)
        g_cvec[j] = b1[j] + red[0][j] + red[1][j] + red[2][j] + red[3][j];
}

// ---------------------------------------------------------------------------
// K1: tensor-core proj. P = embeds @ [W1a | W1b]  (M=n_nodes, N=128, K=128)
// mma.sync.m16n8k8.tf32. 256 thr = 8 warps (2x4), warp tile 64x32,
// K staged in smem chunks of 32. bf16 epilogue straight to g_Pb.
// ---------------------------------------------------------------------------
#define KCHUNK 32
#define APITCH 36      // bank: (36g+tg)%32 = 4g+tg -> 32 distinct, conflict-free
#define BPITCH 136     // bank: (136tg+g)%32 = 8tg+g -> 32 distinct, conflict-free

__device__ __forceinline__ u32 f2tf32(float f) {
    u32 r;
    asm("cvt.rna.tf32.f32 %0, %1;" : "=r"(r) : "f"(f));
    return r;
}

__global__ __launch_bounds__(256) void proj_mma(const float* __restrict__ embeds,
                                                const float* __restrict__ W1,
                                                int n_nodes) {
    __shared__ u32 As[128 * APITCH];     // tf32 bits, [row][k]
    __shared__ u32 Bs[KCHUNK * BPITCH];  // tf32 bits, [k][n]

    const int tid    = threadIdx.x;
    const int warpid = tid >> 5;
    const int lane   = tid & 31;
    const int g      = lane >> 2;   // groupID
    const int tg     = lane & 3;    // thread-in-group
    const int warp_m = warpid & 1;  // 0..1 -> rows warp_m*64
    const int warp_n = warpid >> 1; // 0..3 -> cols warp_n*32
    const int rowBase = blockIdx.x * 128;

    float c[4][4][4];               // [mTile][nTile][reg]
#pragma unroll
    for (int m = 0; m < 4; m++)
#pragma unroll
        for (int n = 0; n < 4; n++)
#pragma unroll
            for (int r = 0; r < 4; r++) c[m][n][r] = 0.f;

    for (int kc = 0; kc < D; kc += KCHUNK) {
        // --- stage A: 128 rows x 32 k = 1024 float4, 4 per thread ---
#pragma unroll
        for (int i = 0; i < 4; i++) {
            int f  = tid + i * 256;
            int r  = f >> 3;
            int k4 = (f & 7) * 4;
            float4 v = make_float4(0.f, 0.f, 0.f, 0.f);
            int gr = rowBase + r;
            if (gr < n_nodes)
                v = *(const float4*)&embeds[(size_t)gr * D + kc + k4];
            u32* p = &As[r * APITCH + k4];
            p[0] = f2tf32(v.x); p[1] = f2tf32(v.y);
            p[2] = f2tf32(v.z); p[3] = f2tf32(v.w);
        }
        // --- stage B: 32 k x 128 n = 1024 float4, 4 per thread ---
#pragma unroll
        for (int i = 0; i < 4; i++) {
            int f  = tid + i * 256;
            int kk = f >> 5;
            int n4 = (f & 31) * 4;
            int kg = kc + kk;
            const float* s = (n4 < HID) ? &W1[kg * HID + n4]
                                        : &W1[(D + kg) * HID + (n4 - HID)];
            float4 v = *(const float4*)s;
            u32* p = &Bs[kk * BPITCH + n4];
            p[0] = f2tf32(v.x); p[1] = f2tf32(v.y);
            p[2] = f2tf32(v.z); p[3] = f2tf32(v.w);
        }
        __syncthreads();

#pragma unroll
        for (int ks = 0; ks < KCHUNK; ks += 8) {
            u32 a[4][4], b[4][2];
#pragma unroll
            for (int m = 0; m < 4; m++) {
                int r0 = warp_m * 64 + m * 16;
                a[m][0] = As[(r0 + g)     * APITCH + ks + tg];
                a[m][1] = As[(r0 + g + 8) * APITCH + ks + tg];
                a[m][2] = As[(r0 + g)     * APITCH + ks + tg + 4];
                a[m][3] = As[(r0 + g + 8) * APITCH + ks + tg + 4];
            }
#pragma unroll
            for (int n = 0; n < 4; n++) {
                int c0 = warp_n * 32 + n * 8 + g;
                b[n][0] = Bs[(ks + tg)     * BPITCH + c0];
                b[n][1] = Bs[(ks + tg + 4) * BPITCH + c0];
            }
#pragma unroll
            for (int m = 0; m < 4; m++)
#pragma unroll
                for (int n = 0; n < 4; n++) {
                    asm volatile(
                        "mma.sync.aligned.m16n8k8.row.col.f32.tf32.tf32.f32 "
                        "{%0,%1,%2,%3}, {%4,%5,%6,%7}, {%8,%9}, {%0,%1,%2,%3};"
                        : "+f"(c[m][n][0]), "+f"(c[m][n][1]),
                          "+f"(c[m][n][2]), "+f"(c[m][n][3])
                        : "r"(a[m][0]), "r"(a[m][1]), "r"(a[m][2]), "r"(a[m][3]),
                          "r"(b[n][0]), "r"(b[n][1]));
                }
        }
        __syncthreads();
    }

    // --- epilogue: C layout rows g, g+8; cols 2*tg, 2*tg+1. Store bf16. ---
#pragma unroll
    for (int m = 0; m < 4; m++) {
        int r0 = rowBase + warp_m * 64 + m * 16;
#pragma unroll
        for (int n = 0; n < 4; n++) {
            int col = warp_n * 32 + n * 8 + tg * 2;
            int ra = r0 + g, rb = r0 + g + 8;
            if (ra < n_nodes)
                *(__nv_bfloat162*)&g_Pb[(size_t)ra * 128 + col] =
                    __floats2bfloat162_rn(c[m][n][0], c[m][n][1]);
            if (rb < n_nodes)
                *(__nv_bfloat162*)&g_Pb[(size_t)rb * 128 + col] =
                    __floats2bfloat162_rn(c[m][n][2], c[m][n][3]);
        }
    }
}

// ---------------------------------------------------------------------------
// K2: one warp per edge, bf16 P gathers (128B per pointer, coalesced).
// ---------------------------------------------------------------------------
__global__ void edge_kernel(const float* __restrict__ W2,
                            const float* __restrict__ b2,
                            const float* __restrict__ u,
                            const int* __restrict__ src,
                            const int* __restrict__ dst,
                            float* __restrict__ out,
                            int E) {
    int warp = (int)((blockIdx.x * blockDim.x + threadIdx.x) >> 5);
    int lane = threadIdx.x & 31;
    if (warp >= E) return;

    int s = __ldg(&src[warp]);
    int d = __ldg(&dst[warp]);
    const __nv_bfloat162* Ps2 = (const __nv_bfloat162*)(g_Pb + (size_t)s * 128);
    const __nv_bfloat162* Pd2 = (const __nv_bfloat162*)(g_Pb + (size_t)d * 128 + 64);

    float2 ps = __bfloat1622float2(Ps2[lane]);
    float2 pd = __bfloat1622float2(Pd2[lane]);
    float2 cv = *(const float2*)&g_cvec[2 * lane];
    float2 w  = *(const float2*)&W2[2 * lane];

    float h0 = fmaxf(ps.x + pd.x + cv.x, 0.f);
    float h1 = fmaxf(ps.y + pd.y + cv.y, 0.f);
    float p = fmaf(h0, w.x, h1 * w.y);

#pragma unroll
    for (int off = 16; off; off >>= 1)
        p += __shfl_xor_sync(0xffffffffu, p, off);

    if (lane == 0) {
        float sw = p + __ldg(&b2[0]);
        float eps = fmaf(-0.9998f, __ldg(&u[warp]), 0.9999f);
        float gate = logf(eps) - log1pf(-eps);
        float x = (gate + sw) * 0.2f;               // TEMP = 5
        out[warp] = 1.f / (1.f + expf(-x));
    }
}

// ---------------------------------------------------------------------------
// Inputs (metadata order): embeds, W1, b1, W2, b2, u, src, dst, n
// ---------------------------------------------------------------------------
extern "C" void kernel_launch(void* const* d_in, const int* in_sizes, int n_in,
                              void* d_out, int out_size) {
    const float* embeds = (const float*)d_in[0];
    const float* W1     = (const float*)d_in[1];
    const float* b1     = (const float*)d_in[2];
    const float* W2     = (const float*)d_in[3];
    const float* b2     = (const float*)d_in[4];
    const float* u      = (const float*)d_in[5];
    const int*   src    = (const int*)d_in[6];
    const int*   dst    = (const int*)d_in[7];
    const int*   n_ptr  = (const int*)d_in[8];

    int n_nodes = in_sizes[0] / D;
    int E       = in_sizes[6];

    cvec_kernel<<<1, 256>>>(embeds, W1, b1, n_ptr);
    proj_mma<<<(n_nodes + 127) / 128, 256>>>(embeds, W1, n_nodes);
    edge_kernel<<<(E + 7) / 8, 256>>>(W2, b2, u, src, dst, (float*)d_out, E);
}

// round 5
// speedup vs baseline: 3.0130x; 2.1368x over previous
#include <cuda_runtime.h>
#include <cuda_bf16.h>
#include <cstdint>
#include <math.h>

typedef unsigned int u32;

#define D 128
#define HID 64

// Per-node projections in bf16: P[i][0:64] = embeds[i] @ W1[0:128,:]
//                               P[i][64:128] = embeds[i] @ W1[128:256,:]
__device__ __nv_bfloat16 g_Pb[(size_t)50000 * 2 * HID];
// Constant part: embeds[n] @ W1[256:384,:] + b1  (fp32)
__device__ __align__(16) float g_cvec[HID];

// ---------------------------------------------------------------------------
// cp.async helpers
// ---------------------------------------------------------------------------
__device__ __forceinline__ void cpa16(u32 saddr, const void* g, int bytes) {
    asm volatile("cp.async.cg.shared.global [%0], [%1], 16, %2;"
                 :: "r"(saddr), "l"(g), "r"(bytes));
}
__device__ __forceinline__ void cpa_commit() {
    asm volatile("cp.async.commit_group;");
}
template <int N>
__device__ __forceinline__ void cpa_wait() {
    asm volatile("cp.async.wait_group %0;" :: "n"(N));
}

// ---------------------------------------------------------------------------
// K1: tensor-core proj (+ folded cvec in the last block).
// P = embeds @ [W1a | W1b]  (M=n_nodes, N=128, K=128)
// mma.sync.m16n8k8.tf32 (raw fp32 bits; HW truncates to tf32).
// 256 thr = 8 warps (2x4), warp tile 64x32.
// K pipelined in chunks of 16 via cp.async double buffering.
// ---------------------------------------------------------------------------
#define KCHUNK 16
#define APITCH 20      // (20g+tg)%32 distinct over 32 lanes -> conflict-free
#define BPITCH 136     // (8tg+g)%32 distinct -> conflict-free

__global__ __launch_bounds__(256) void proj_mma(const float* __restrict__ embeds,
                                                const float* __restrict__ W1,
                                                const float* __restrict__ b1,
                                                const int* __restrict__ n_ptr,
                                                int n_nodes) {
    __shared__ u32 As[2][128 * APITCH];   // 2 x 10240 B
    __shared__ u32 Bs[2][KCHUNK * BPITCH];// 2 x  8704 B

    const int tid = threadIdx.x;

    // ---- last block: compute cvec (runs concurrently with proj blocks) ----
    if (blockIdx.x == gridDim.x - 1) {
        float* red = (float*)As;          // reuse smem
        int t = tid >> 6;
        int j = tid & 63;
        int n = n_ptr[0];
        const float* e = embeds + (size_t)n * D;
        float acc = 0.f;
#pragma unroll 8
        for (int k = t * 32; k < t * 32 + 32; k++)
            acc = fmaf(e[k], W1[(2 * D + k) * HID + j], acc);
        red[t * HID + j] = acc;
        __syncthreads();
        if (t == 0)
            g_cvec[j] = b1[j] + red[0 * HID + j] + red[1 * HID + j] +
                        red[2 * HID + j] + red[3 * HID + j];
        return;
    }

    const int warpid = tid >> 5;
    const int lane   = tid & 31;
    const int g      = lane >> 2;
    const int tg     = lane & 3;
    const int warp_m = warpid & 1;
    const int warp_n = warpid >> 1;
    const int rowBase = blockIdx.x * 128;

    u32 sAs = (u32)__cvta_generic_to_shared(&As[0][0]);
    u32 sBs = (u32)__cvta_generic_to_shared(&Bs[0][0]);

    // per-thread staging coords (2 float4 each for A and B)
    // A: f = tid + i*256 ; r = f>>2 ; k4 = (f&3)*4
    // B: f = tid + i*256 ; kk = f>>5 ; n4 = (f&31)*4
    auto stage = [&](int buf, int kc) {
#pragma unroll
        for (int i = 0; i < 2; i++) {
            int f  = tid + i * 256;
            int r  = f >> 2;
            int k4 = (f & 3) * 4;
            int gr = rowBase + r;
            int bytes = (gr < n_nodes) ? 16 : 0;
            const float* gp = &embeds[(size_t)(gr < n_nodes ? gr : 0) * D + kc + k4];
            cpa16(sAs + (buf * 128 * APITCH + r * APITCH + k4) * 4, gp, bytes);
        }
#pragma unroll
        for (int i = 0; i < 2; i++) {
            int f  = tid + i * 256;
            int kk = f >> 5;
            int n4 = (f & 31) * 4;
            int kg = kc + kk;
            const float* gp = (n4 < HID) ? &W1[kg * HID + n4]
                                         : &W1[(D + kg) * HID + (n4 - HID)];
            cpa16(sBs + (buf * KCHUNK * BPITCH + kk * BPITCH + n4) * 4, gp, 16);
        }
        cpa_commit();
    };

    float c[4][4][4];
#pragma unroll
    for (int m = 0; m < 4; m++)
#pragma unroll
        for (int n = 0; n < 4; n++)
#pragma unroll
            for (int r = 0; r < 4; r++) c[m][n][r] = 0.f;

    stage(0, 0);

    const int NITER = D / KCHUNK;   // 8
    for (int it = 0; it < NITER; it++) {
        int buf = it & 1;
        if (it < NITER - 1) stage(buf ^ 1, (it + 1) * KCHUNK);
        if (it < NITER - 1) cpa_wait<1>(); else cpa_wait<0>();
        __syncthreads();

        const u32* A = &As[buf][0];
        const u32* B = &Bs[buf][0];
#pragma unroll
        for (int ks = 0; ks < KCHUNK; ks += 8) {
            u32 a[4][4], b[4][2];
#pragma unroll
            for (int m = 0; m < 4; m++) {
                int r0 = warp_m * 64 + m * 16;
                a[m][0] = A[(r0 + g)     * APITCH + ks + tg];
                a[m][1] = A[(r0 + g + 8) * APITCH + ks + tg];
                a[m][2] = A[(r0 + g)     * APITCH + ks + tg + 4];
                a[m][3] = A[(r0 + g + 8) * APITCH + ks + tg + 4];
            }
#pragma unroll
            for (int n = 0; n < 4; n++) {
                int c0 = warp_n * 32 + n * 8 + g;
                b[n][0] = B[(ks + tg)     * BPITCH + c0];
                b[n][1] = B[(ks + tg + 4) * BPITCH + c0];
            }
#pragma unroll
            for (int m = 0; m < 4; m++)
#pragma unroll
                for (int n = 0; n < 4; n++) {
                    asm volatile(
                        "mma.sync.aligned.m16n8k8.row.col.f32.tf32.tf32.f32 "
                        "{%0,%1,%2,%3}, {%4,%5,%6,%7}, {%8,%9}, {%0,%1,%2,%3};"
                        : "+f"(c[m][n][0]), "+f"(c[m][n][1]),
                          "+f"(c[m][n][2]), "+f"(c[m][n][3])
                        : "r"(a[m][0]), "r"(a[m][1]), "r"(a[m][2]), "r"(a[m][3]),
                          "r"(b[n][0]), "r"(b[n][1]));
                }
        }
        __syncthreads();
    }

    // epilogue: rows g, g+8; cols 2*tg, 2*tg+1 -> bf16
#pragma unroll
    for (int m = 0; m < 4; m++) {
        int r0 = rowBase + warp_m * 64 + m * 16;
#pragma unroll
        for (int n = 0; n < 4; n++) {
            int col = warp_n * 32 + n * 8 + tg * 2;
            int ra = r0 + g, rb = r0 + g + 8;
            if (ra < n_nodes)
                *(__nv_bfloat162*)&g_Pb[(size_t)ra * 128 + col] =
                    __floats2bfloat162_rn(c[m][n][0], c[m][n][1]);
            if (rb < n_nodes)
                *(__nv_bfloat162*)&g_Pb[(size_t)rb * 128 + col] =
                    __floats2bfloat162_rn(c[m][n][2], c[m][n][3]);
        }
    }
}

// ---------------------------------------------------------------------------
// K2: 4 edges per warp (8 lanes each). 16B bf16 gathers; fast-math tail
// executed once per warp for all 4 edges (lanes 0/8/16/24 predicated on).
// ---------------------------------------------------------------------------
__global__ __launch_bounds__(256) void edge_kernel(const float* __restrict__ W2,
                            const float* __restrict__ b2,
                            const float* __restrict__ u,
                            const int* __restrict__ src,
                            const int* __restrict__ dst,
                            float* __restrict__ out,
                            int E) {
    int gidx = blockIdx.x * blockDim.x + threadIdx.x;
    int warp = gidx >> 5;
    int lane = threadIdx.x & 31;
    int q = lane >> 3;          // quarter id 0..3
    int l = lane & 7;           // lane within quarter
    int e = warp * 4 + q;
    if (e >= E) return;

    int s = __ldg(&src[e]);
    int d = __ldg(&dst[e]);
    const uint4* Ps = (const uint4*)(g_Pb + (size_t)s * 128);       // 64 bf16
    const uint4* Pd = (const uint4*)(g_Pb + (size_t)d * 128 + 64);  // 64 bf16
    uint4 pu = Ps[l];
    uint4 du = Pd[l];
    float4 c0 = *(const float4*)&g_cvec[8 * l];
    float4 c1 = *(const float4*)&g_cvec[8 * l + 4];
    float4 w0 = *(const float4*)&W2[8 * l];
    float4 w1 = *(const float4*)&W2[8 * l + 4];

    float2 pA = __bfloat1622float2(*(const __nv_bfloat162*)&pu.x);
    float2 pB = __bfloat1622float2(*(const __nv_bfloat162*)&pu.y);
    float2 pC = __bfloat1622float2(*(const __nv_bfloat162*)&pu.z);
    float2 pD = __bfloat1622float2(*(const __nv_bfloat162*)&pu.w);
    float2 dA = __bfloat1622float2(*(const __nv_bfloat162*)&du.x);
    float2 dB = __bfloat1622float2(*(const __nv_bfloat162*)&du.y);
    float2 dC = __bfloat1622float2(*(const __nv_bfloat162*)&du.z);
    float2 dD = __bfloat1622float2(*(const __nv_bfloat162*)&du.w);

    float h0 = fmaxf(pA.x + dA.x + c0.x, 0.f);
    float h1 = fmaxf(pA.y + dA.y + c0.y, 0.f);
    float h2 = fmaxf(pB.x + dB.x + c0.z, 0.f);
    float h3 = fmaxf(pB.y + dB.y + c0.w, 0.f);
    float h4 = fmaxf(pC.x + dC.x + c1.x, 0.f);
    float h5 = fmaxf(pC.y + dC.y + c1.y, 0.f);
    float h6 = fmaxf(pD.x + dD.x + c1.z, 0.f);
    float h7 = fmaxf(pD.y + dD.y + c1.w, 0.f);

    float acc = h0 * w0.x;
    acc = fmaf(h1, w0.y, acc);
    acc = fmaf(h2, w0.z, acc);
    acc = fmaf(h3, w0.w, acc);
    acc = fmaf(h4, w1.x, acc);
    acc = fmaf(h5, w1.y, acc);
    acc = fmaf(h6, w1.z, acc);
    acc = fmaf(h7, w1.w, acc);

    acc += __shfl_xor_sync(0xffffffffu, acc, 4);
    acc += __shfl_xor_sync(0xffffffffu, acc, 2);
    acc += __shfl_xor_sync(0xffffffffu, acc, 1);

    if (l == 0) {
        float sw = acc + __ldg(&b2[0]);
        float eps = fmaf(-0.9998f, __ldg(&u[e]), 0.9999f);
        // gate/TEMP = (ln2/5) * (log2(eps) - log2(1-eps))
        float gate5 = 0.13862944f * (__log2f(eps) - __log2f(1.f - eps));
        float z = gate5 + sw * 0.2f;                 // TEMP = 5
        out[e] = 1.f / (1.f + __expf(-z));
    }
}

// ---------------------------------------------------------------------------
// Inputs (metadata order): embeds, W1, b1, W2, b2, u, src, dst, n
// ---------------------------------------------------------------------------
extern "C" void kernel_launch(void* const* d_in, const int* in_sizes, int n_in,
                              void* d_out, int out_size) {
    const float* embeds = (const float*)d_in[0];
    const float* W1     = (const float*)d_in[1];
    const float* b1     = (const float*)d_in[2];
    const float* W2     = (const float*)d_in[3];
    const float* b2     = (const float*)d_in[4];
    const float* u      = (const float*)d_in[5];
    const int*   src    = (const int*)d_in[6];
    const int*   dst    = (const int*)d_in[7];
    const int*   n_ptr  = (const int*)d_in[8];

    int n_nodes = in_sizes[0] / D;
    int E       = in_sizes[6];

    int nb = (n_nodes + 127) / 128;
    proj_mma<<<nb + 1, 256>>>(embeds, W1, b1, n_ptr, n_nodes);

    int warps = (E + 3) / 4;
    int blocks = (warps * 32 + 255) / 256;
    edge_kernel<<<blocks, 256>>>(W2, b2, u, src, dst, (float*)d_out, E);
}